// round 16
// baseline (speedup 1.0000x reference)
#include <cuda_runtime.h>
#include <math.h>

#define CIN     512
#define NTAB    550            // 10+20+...+100 quadrature points
#define LOG2E   1.4426950408889634f
#define EPSQ    1e-5f
#define NBLK    176            // 1408 warps total (~9/SM)
#define NTHR    256

__device__ __forceinline__ float ex2f(float x) {
    float r;
    asm("ex2.approx.f32 %0, %1;" : "=f"(r) : "f"(x));
    return r;
}
__device__ __forceinline__ float dot4(float4 a, float4 b) {
    return fmaf(a.x, b.x, fmaf(a.y, b.y, fmaf(a.z, b.z, a.w * b.w)));
}

// ---------------------------------------------------------------------------
// Intra-warp software pipeline, zero synchronization. Each warp walks its
// tiles (32 rows each); iteration over tile t fuses, per GEMV row r:
//     1. issue row r's 4x LDG.128 (tile t)
//     2. run a ~17-point slice of tile t-1's quadrature  <- hides LDG latency
//     3. FMA-reduce + shfl row r
// The 10 grids are INDEPENDENT quadratures (not prefixes): the accumulator
// resets at each grid boundary, recording that grid's own sum S_g; the
// epilogue computes prob[g] = S_g - S_{g-1} and normalizes by S_9.
// ---------------------------------------------------------------------------
__global__ void __launch_bounds__(NTHR)
beta_wavepipe_kernel(const float* __restrict__ x,
                     const float* __restrict__ Wa, const float* __restrict__ ba,
                     const float* __restrict__ Wb, const float* __restrict__ bb,
                     float* __restrict__ out, int B)
{
    __shared__ float2 tab[NTAB];          // (log t, log1p(-t)) * log2e
    __shared__ float  scdf[NTHR][11];     // 10 grid sums/thread (+1 pad)

    const int tid  = threadIdx.x;
    const int lane = tid & 31;
    const int wid  = tid >> 5;

    // ---- build quadrature table (row-independent) ----
    for (int k = tid; k < NTAB; k += NTHR) {
        int g = 0, off = 0;                        // grid g: 10(g+1) pts @ off
        while (k >= off + 10 * (g + 1)) { off += 10 * (g + 1); ++g; }
        int n = 10 * (g + 1);
        int j = k - off;
        float bthr = 0.1f * (float)(g + 1);
        float step = (bthr - 2.f * EPSQ) / (float)(n - 1);
        float t = fmaf(step, (float)j, EPSQ);
        tab[k] = make_float2(logf(t) * LOG2E, log1pf(-t) * LOG2E);
    }
    __syncthreads();

    // ---- weights register-resident (4KB, L1-fed) ----
    const float4* wa4 = reinterpret_cast<const float4*>(Wa);
    const float4* wb4 = reinterpret_cast<const float4*>(Wb);
    const float4 av0 = __ldg(wa4 + lane),      av1 = __ldg(wa4 + lane + 32);
    const float4 av2 = __ldg(wa4 + lane + 64), av3 = __ldg(wa4 + lane + 96);
    const float4 bv0 = __ldg(wb4 + lane),      bv1 = __ldg(wb4 + lane + 32);
    const float4 bv2 = __ldg(wb4 + lane + 64), bv3 = __ldg(wb4 + lane + 96);
    const float biasa = ba[0], biasb = bb[0];

    const int ntiles = (B + 31) >> 5;
    const int nwarps = NBLK * (NTHR >> 5);
    const int gw     = blockIdx.x * (NTHR >> 5) + wid;

    // pipeline state for the in-flight quadrature (previous tile), per lane
    bool  pvalid = false;
    int   prow   = 0;
    float a1 = 0.f, b1 = 0.f, c2 = 0.f, s = 0.f;
    int   kc = 0, nb = 0, binc = 0;
    float* psm = &scdf[tid][0];

    for (int tile = gw; ; tile += nwarps) {
        const bool cvalid = tile < ntiles;
        if (!cvalid && !pvalid) break;
        const int base = tile << 5;

        float za = 0.f, zb = 0.f;                  // new tile's logits (lane r)
#pragma unroll 1
        for (int r = 0; r < 32; ++r) {
            // --- 1. issue current tile row r's loads ---
            float4 x0, x1, x2, x3;
            x0 = x1 = x2 = x3 = make_float4(0.f, 0.f, 0.f, 0.f);
            const bool ldrow = cvalid && (base + r < B);   // warp-uniform
            if (ldrow) {
                const float4* xr = reinterpret_cast<const float4*>(x)
                                 + (size_t)(base + r) * (CIN / 4);
                x0 = __ldcs(xr + lane);      x1 = __ldcs(xr + lane + 32);
                x2 = __ldcs(xr + lane + 64); x3 = __ldcs(xr + lane + 96);
            }
            // --- 2. quadrature slice of previous tile (hides LDG latency) ---
            if (pvalid) {
                const int ktarget = ((r + 1) * NTAB) >> 5;   // r=31 -> 550
                for (; kc < ktarget; ++kc) {
                    float2 uv = tab[kc];
                    s += ex2f(fmaf(a1, uv.x, fmaf(b1, uv.y, c2)));
                    if (kc + 1 == nb) {        // grid boundary: record sum,
                        *psm++ = s;            // then RESET (grids are
                        s = 0.f;               // independent quadratures)
                        nb += binc; binc += 10;
                    }
                }
            }
            // --- 3. reduce current row (warp-uniform shfl) ---
            if (cvalid) {
                float sa = (dot4(x0, av0) + dot4(x1, av1))
                         + (dot4(x2, av2) + dot4(x3, av3));
                float sb = (dot4(x0, bv0) + dot4(x1, bv1))
                         + (dot4(x2, bv2) + dot4(x3, bv3));
#pragma unroll
                for (int off = 16; off; off >>= 1) {
                    sa += __shfl_xor_sync(0xffffffffu, sa, off);
                    sb += __shfl_xor_sync(0xffffffffu, sb, off);
                }
                if (lane == r) { za = sa + biasa; zb = sb + biasb; }
            }
        }

        // --- finalize previous tile: prob[g] = S_g - S_{g-1}, normalize ---
        if (pvalid && prow < B) {
            const float* q = &scdf[tid][0];
            const float inv = 1.f / q[9];
            float* o = out + (size_t)prow * 10;
            float prev = 0.f;
#pragma unroll
            for (int g = 0; g < 10; ++g) {
                float cg = q[g];
                o[g] = (cg - prev) * inv;
                prev = cg;
            }
        }

        // --- promote current tile's logits into quadrature state ---
        if (cvalid) {
            prow = base + lane;
            // stable softplus == jax.nn.softplus
            float spa = (za > 0.f) ? (za + log1pf(expf(-za))) : log1pf(expf(za));
            float spb = (zb > 0.f) ? (zb + log1pf(expf(-zb))) : log1pf(expf(zb));
            float alpha = fminf(1.f + spa, 100.f);
            float beta  = fminf(1.f + spb, 100.f);
            float lb = lgammaf(alpha) + lgammaf(beta) - lgammaf(alpha + beta);
            a1 = alpha - 1.f;
            b1 = beta - 1.f;
            c2 = -lb * LOG2E;      // dx & exp(-lbeta) cancel in normalization
            s  = 0.f; kc = 0; nb = 10; binc = 20;
            psm = &scdf[tid][0];
            pvalid = true;
        } else {
            pvalid = false;
        }
    }
}

// ---------------------------------------------------------------------------
extern "C" void kernel_launch(void* const* d_in, const int* in_sizes, int n_in,
                              void* d_out, int out_size)
{
    const float* x  = (const float*)d_in[0];
    const float* Wa = (const float*)d_in[1];
    const float* ba = (const float*)d_in[2];
    const float* Wb = (const float*)d_in[3];
    const float* bb = (const float*)d_in[4];

    int B = in_sizes[0] / CIN;
    beta_wavepipe_kernel<<<NBLK, NTHR>>>(x, Wa, ba, Wb, bb, (float*)d_out, B);
}